// round 9
// baseline (speedup 1.0000x reference)
#include <cuda_runtime.h>
#include <cuda_bf16.h>
#include <math.h>
#include <stdint.h>

#define N_TOK 16384
#define D_DIM 1024
#define E_NUM 16
#define H_DIM 4096
#define NC_DIM 1000
#define CAP 2048
#define NB_GATE (N_TOK/8)

// ---------------- device scratch ----------------
__device__ __align__(16) int8_t g_dq1[(size_t)E_NUM*CAP*D_DIM];
__device__ __align__(16) int8_t g_dq2[(size_t)E_NUM*CAP*D_DIM];
__device__ float  g_ds[E_NUM*CAP];
__device__ __align__(16) int8_t g_w1q1[(size_t)E_NUM*H_DIM*D_DIM];
__device__ __align__(16) int8_t g_w1q2[(size_t)E_NUM*H_DIM*D_DIM];
__device__ float  g_w1m[E_NUM*H_DIM];
__device__ __align__(16) int8_t g_w2q1[(size_t)E_NUM*D_DIM*H_DIM];
__device__ __align__(16) int8_t g_w2q2[(size_t)E_NUM*D_DIM*H_DIM];
__device__ float  g_w2m[E_NUM*D_DIM];
__device__ __align__(16) int8_t g_wlq1[(size_t)1024*D_DIM];
__device__ __align__(16) int8_t g_wlq2[(size_t)1024*D_DIM];
__device__ float  g_wlm[1024];
__device__ __align__(16) float  g_h[(size_t)E_NUM*CAP*H_DIM];
__device__ __align__(16) int8_t g_hq1[(size_t)E_NUM*CAP*H_DIM];
__device__ __align__(16) int8_t g_hq2[(size_t)E_NUM*CAP*H_DIM];
__device__ float  g_hs[E_NUM*CAP];
__device__ __align__(16) float  g_oute[(size_t)E_NUM*CAP*D_DIM];
__device__ __align__(16) int8_t g_yq1[(size_t)N_TOK*D_DIM];
__device__ __align__(16) int8_t g_yq2[(size_t)N_TOK*D_DIM];
__device__ float  g_ys[N_TOK];
__device__ int   g_idx[N_TOK];
__device__ float g_gate[N_TOK];
__device__ int   g_lrank[N_TOK];
__device__ int   g_bhist[NB_GATE][E_NUM];
__device__ float g_bprob[NB_GATE][E_NUM];
__device__ int   g_boff[NB_GATE][E_NUM];
__device__ int   g_count[E_NUM];
__device__ float g_probsum[E_NUM];
__device__ int   g_pos[N_TOK];

// ---------------- PTX helpers ----------------
__device__ __forceinline__ uint32_t smem_u32(const void* p) {
    return (uint32_t)__cvta_generic_to_shared(p);
}
__device__ __forceinline__ void cpa(uint32_t dst, const void* src) {
    asm volatile("cp.async.cg.shared.global [%0], [%1], 16;" :: "r"(dst), "l"(src) : "memory");
}
__device__ __forceinline__ void cpa_commit() { asm volatile("cp.async.commit_group;" ::: "memory"); }
template<int N> __device__ __forceinline__ void cpa_wait() {
    asm volatile("cp.async.wait_group %0;" :: "n"(N) : "memory");
}
__device__ __forceinline__ void ldsm4(uint32_t* r, uint32_t a) {
    asm volatile("ldmatrix.sync.aligned.m8n8.x4.shared.b16 {%0,%1,%2,%3}, [%4];"
                 : "=r"(r[0]), "=r"(r[1]), "=r"(r[2]), "=r"(r[3]) : "r"(a));
}
__device__ __forceinline__ void mma_s8(int* d, const uint32_t* a, const uint32_t* b) {
    asm volatile(
        "mma.sync.aligned.m16n8k32.row.col.s32.s8.s8.s32 "
        "{%0,%1,%2,%3}, {%4,%5,%6,%7}, {%8,%9}, {%0,%1,%2,%3};"
        : "+r"(d[0]), "+r"(d[1]), "+r"(d[2]), "+r"(d[3])
        : "r"(a[0]), "r"(a[1]), "r"(a[2]), "r"(a[3]), "r"(b[0]), "r"(b[1]));
}

__device__ __forceinline__ void quant1(float v, float inv, int8_t& q1, int8_t& q2) {
    float t = v * inv;
    float a1 = rintf(t); a1 = fminf(fmaxf(a1, -127.f), 127.f);
    float a2 = rintf((t - a1) * 254.f); a2 = fminf(fmaxf(a2, -127.f), 127.f);
    q1 = (int8_t)(int)a1; q2 = (int8_t)(int)a2;
}
__device__ __forceinline__ float blockmax(float v, float* red, int tid) {
    red[tid] = v; __syncthreads();
    for (int o = 128; o > 0; o >>= 1) {
        if (tid < o) red[tid] = fmaxf(red[tid], red[tid + o]);
        __syncthreads();
    }
    return red[0];
}

// ---------------- gating ----------------
__global__ void k_gate(const float* __restrict__ x, const float* __restrict__ Wg) {
    int warp = threadIdx.x >> 5, lane = threadIdx.x & 31;
    int t = blockIdx.x * 8 + warp;
    __shared__ float s_prob[E_NUM];
    __shared__ int s_idx[8];
    if (threadIdx.x < E_NUM) s_prob[threadIdx.x] = 0.f;
    __syncthreads();
    float acc[E_NUM];
#pragma unroll
    for (int e = 0; e < E_NUM; e++) acc[e] = 0.f;
    const float* xr = x + (size_t)t * D_DIM;
    for (int j = 0; j < D_DIM / 32; j++) {
        float xv = xr[lane + 32 * j];
        const float* wr = Wg + (size_t)(lane + 32 * j) * E_NUM;
#pragma unroll
        for (int e = 0; e < E_NUM; e++) acc[e] = fmaf(xv, __ldg(wr + e), acc[e]);
    }
#pragma unroll
    for (int e = 0; e < E_NUM; e++)
#pragma unroll
        for (int o = 16; o > 0; o >>= 1) acc[e] += __shfl_xor_sync(0xffffffffu, acc[e], o);
    if (lane == 0) {
        float m = acc[0]; int ai = 0;
#pragma unroll
        for (int e = 1; e < E_NUM; e++) if (acc[e] > m) { m = acc[e]; ai = e; }
        float p[E_NUM]; float s = 0.f;
#pragma unroll
        for (int e = 0; e < E_NUM; e++) { p[e] = expf(acc[e] - m); s += p[e]; }
        float inv = 1.f / s;
#pragma unroll
        for (int e = 0; e < E_NUM; e++) atomicAdd(&s_prob[e], p[e] * inv);
        g_idx[t] = ai; g_gate[t] = p[ai] * inv; s_idx[warp] = ai;
    }
    __syncthreads();
    if (threadIdx.x == 0) {
        int cnt[E_NUM];
#pragma unroll
        for (int e = 0; e < E_NUM; e++) cnt[e] = 0;
#pragma unroll
        for (int w = 0; w < 8; w++) {
            int e = s_idx[w];
            g_lrank[blockIdx.x * 8 + w] = cnt[e];
            cnt[e]++;
        }
#pragma unroll
        for (int e = 0; e < E_NUM; e++) g_bhist[blockIdx.x][e] = cnt[e];
    }
    if (threadIdx.x < E_NUM) g_bprob[blockIdx.x][threadIdx.x] = s_prob[threadIdx.x];
}

// ---------------- scan + probsum reduce + pad quantized dispatch ----------
__global__ void k_scan() {
    const int PB = NB_GATE / 256;
    int e = blockIdx.x, tid = threadIdx.x;
    int v[PB]; int s = 0;
    float ps = 0.f;
#pragma unroll
    for (int i = 0; i < PB; i++) {
        v[i] = g_bhist[tid * PB + i][e];
        s += v[i];
        ps += g_bprob[tid * PB + i][e];
    }
    __shared__ int sh[256];
    __shared__ float sp[256];
    sh[tid] = s; sp[tid] = ps;
    __syncthreads();
    for (int o = 1; o < 256; o <<= 1) {
        int q = (tid >= o) ? sh[tid - o] : 0;
        __syncthreads(); sh[tid] += q; __syncthreads();
    }
    int off = sh[tid] - s;
#pragma unroll
    for (int i = 0; i < PB; i++) { g_boff[tid * PB + i][e] = off; off += v[i]; }
    for (int o = 128; o > 0; o >>= 1) {
        if (tid < o) sp[tid] += sp[tid + o];
        __syncthreads();
    }
    if (tid == 0) { g_count[e] = sh[255]; g_probsum[e] = sp[0]; }
    __syncthreads();
    int c = sh[255]; if (c > CAP) c = CAP;
    int r1 = (c + 127) & ~127; if (r1 > CAP) r1 = CAP;
    for (int r = c; r < r1; r++) {
        size_t o = (size_t)(e * CAP + r) * 256 + tid;   // int index (1024B/4)
        ((int*)g_dq1)[o] = 0;
        ((int*)g_dq2)[o] = 0;
        if (tid == 0) g_ds[e * CAP + r] = 0.f;
    }
}

// ---------------- column-abs-max for weights (atomicMax, idempotent) ------
__global__ void k_cmax(const float* __restrict__ W1, const float* __restrict__ W2,
                       const float* __restrict__ Wl) {
    int b = blockIdx.x, tid = threadIdx.x;
    if (b < 1024) {                       // W1: e(16) x nb(16) x ks(4)
        int e = b >> 6, rem = b & 63, nb = rem >> 2, ks = rem & 3;
        int n = nb * 256 + tid;
        const float* p = W1 + (size_t)e * D_DIM * H_DIM + (size_t)(ks * 256) * H_DIM + n;
        float m = 0.f;
#pragma unroll 8
        for (int k = 0; k < 256; k++) m = fmaxf(m, fabsf(p[(size_t)k * H_DIM]));
        atomicMax((int*)&g_w1m[e * H_DIM + n], __float_as_int(m));
    } else if (b < 2048) {                // W2: e(16) x nb(4) x ks(16)
        int i = b - 1024;
        int e = i >> 6, rem = i & 63, nb = rem >> 4, ks = rem & 15;
        int n = nb * 256 + tid;
        const float* p = W2 + (size_t)e * H_DIM * D_DIM + (size_t)(ks * 256) * D_DIM + n;
        float m = 0.f;
#pragma unroll 8
        for (int k = 0; k < 256; k++) m = fmaxf(m, fabsf(p[(size_t)k * D_DIM]));
        atomicMax((int*)&g_w2m[e * D_DIM + n], __float_as_int(m));
    } else {                              // Wl: nb(4) x ks(4)
        int i = b - 2048;
        int nb = i >> 2, ks = i & 3;
        int n = nb * 256 + tid;
        if (n < NC_DIM) {
            const float* p = Wl + (size_t)(ks * 256) * NC_DIM + n;
            float m = 0.f;
#pragma unroll 8
            for (int k = 0; k < 256; k++) m = fmaxf(m, fabsf(p[(size_t)k * NC_DIM]));
            atomicMax((int*)&g_wlm[n], __float_as_int(m));
        }
    }
}

// ---------------- transpose + quantize weights -----------------------------
__device__ __forceinline__ void wquant_body(
    const float* __restrict__ in, int8_t* __restrict__ q1, int8_t* __restrict__ q2,
    const float* __restrict__ sc, int R, int C, int CpN,
    int bx, int by, int bz, int tid)
{
    __shared__ float s[32][33];
    const float* ip = in + (size_t)bz * R * C;
    int c0 = bx * 32, r0 = by * 32;
    int tx = tid & 31, ty = tid >> 5;
#pragma unroll
    for (int k = 0; k < 4; k++) {
        int r = r0 + ty + 8 * k, c = c0 + tx;
        s[ty + 8 * k][tx] = (c < C) ? ip[(size_t)r * C + c] : 0.f;
    }
    __syncthreads();
#pragma unroll
    for (int k = 0; k < 4; k++) {
        int cc = ty + 8 * k;
        int n = c0 + cc;
        float mx = sc[(size_t)bz * CpN + n];
        float inv = 126.f / fmaxf(mx, 1e-30f);
        int8_t a1, a2;
        quant1(s[tx][cc], inv, a1, a2);
        size_t o = ((size_t)bz * CpN + n) * R + r0 + tx;
        q1[o] = a1; q2[o] = a2;
    }
}

#define BIG_W1 16384
#define BIG_W2 (16384 + 65536)
#define BIG_WL (16384 + 2*65536)
#define BIG_TOT (16384 + 2*65536 + 1024)

__global__ void k_big(const float* __restrict__ x, const float* __restrict__ W1,
                      const float* __restrict__ W2, const float* __restrict__ Wl) {
    int b = blockIdx.x, tid = threadIdx.x;
    if (b < BIG_W1) {
        __shared__ float red[256];
        __shared__ float s_inv;
        int t = b;
        int e = g_idx[t];
        int pos = g_boff[t >> 3][e] + g_lrank[t];
        if (pos >= CAP) { if (tid == 0) g_pos[t] = -1; return; }
        float4 v = ((const float4*)(x + (size_t)t * D_DIM))[tid];
        float m = fmaxf(fmaxf(fabsf(v.x), fabsf(v.y)), fmaxf(fabsf(v.z), fabsf(v.w)));
        float M = blockmax(m, red, tid);
        if (tid == 0) {
            g_ds[e * CAP + pos] = M;
            s_inv = 126.f / fmaxf(M, 1e-30f);
            g_pos[t] = pos;
        }
        __syncthreads();
        float inv = s_inv;
        char4 q1v, q2v;
        quant1(v.x, inv, (int8_t&)q1v.x, (int8_t&)q2v.x);
        quant1(v.y, inv, (int8_t&)q1v.y, (int8_t&)q2v.y);
        quant1(v.z, inv, (int8_t&)q1v.z, (int8_t&)q2v.z);
        quant1(v.w, inv, (int8_t&)q1v.w, (int8_t&)q2v.w);
        size_t o = (size_t)(e * CAP + pos) * 256 + tid;
        ((char4*)g_dq1)[o] = q1v;
        ((char4*)g_dq2)[o] = q2v;
    } else if (b < BIG_W2) {
        int i = b - BIG_W1;     // W1: [e,1024,4096] -> q [e,4096,1024]
        int bx = i % 128, by = (i / 128) % 32, bz = i / (128 * 32);
        wquant_body(W1, g_w1q1, g_w1q2, g_w1m, D_DIM, H_DIM, H_DIM, bx, by, bz, tid);
    } else if (b < BIG_WL) {
        int i = b - BIG_W2;     // W2: [e,4096,1024] -> q [e,1024,4096]
        int bx = i % 32, by = (i / 32) % 128, bz = i / (32 * 128);
        wquant_body(W2, g_w2q1, g_w2q2, g_w2m, H_DIM, D_DIM, D_DIM, bx, by, bz, tid);
    } else {
        int i = b - BIG_WL;     // Wl: [1024,1000] -> q [1024,1024]
        int bx = i % 32, by = i / 32;
        wquant_body(Wl, g_wlq1, g_wlq2, g_wlm, D_DIM, NC_DIM, 1024, bx, by, 0, tid);
    }
}

// ---------------- quantize hidden activations ------------------------------
__global__ void k_hquant() {
    __shared__ float red[256];
    __shared__ float s_inv;
    int b = blockIdx.x, tid = threadIdx.x;
    int e = b >> 11, r = b & 2047;
    int c = g_count[e]; if (c > CAP) c = CAP;
    int r1 = (c + 127) & ~127; if (r1 > CAP) r1 = CAP;
    if (r >= r1) return;
    const float4* hr = (const float4*)(g_h + (size_t)(e * CAP + r) * H_DIM);
    float4 a[4];
    float m = 0.f;
#pragma unroll
    for (int i = 0; i < 4; i++) {
        a[i] = hr[tid + i * 256];
        m = fmaxf(m, fmaxf(fmaxf(fabsf(a[i].x), fabsf(a[i].y)),
                           fmaxf(fabsf(a[i].z), fabsf(a[i].w))));
    }
    float M = blockmax(m, red, tid);
    if (tid == 0) { g_hs[e * CAP + r] = M; s_inv = 126.f / fmaxf(M, 1e-30f); }
    __syncthreads();
    float inv = s_inv;
    size_t base = (size_t)(e * CAP + r) * 1024;
#pragma unroll
    for (int i = 0; i < 4; i++) {
        char4 q1v, q2v;
        quant1(a[i].x, inv, (int8_t&)q1v.x, (int8_t&)q2v.x);
        quant1(a[i].y, inv, (int8_t&)q1v.y, (int8_t&)q2v.y);
        quant1(a[i].z, inv, (int8_t&)q1v.z, (int8_t&)q2v.z);
        quant1(a[i].w, inv, (int8_t&)q1v.w, (int8_t&)q2v.w);
        ((char4*)g_hq1)[base + tid + i * 256] = q1v;
        ((char4*)g_hq2)[base + tid + i * 256] = q2v;
    }
}

// ---------------- combine + quantize y --------------------------------------
__global__ void k_combine() {
    __shared__ float red[256];
    __shared__ float s_inv;
    int t = blockIdx.x, tid = threadIdx.x;
    int pos = g_pos[t];
    float4 v = make_float4(0.f, 0.f, 0.f, 0.f);
    if (pos >= 0) {
        int e = g_idx[t];
        float g = g_gate[t];
        v = ((const float4*)(g_oute + ((size_t)e * CAP + pos) * D_DIM))[tid];
        v.x *= g; v.y *= g; v.z *= g; v.w *= g;
    }
    float m = fmaxf(fmaxf(fabsf(v.x), fabsf(v.y)), fmaxf(fabsf(v.z), fabsf(v.w)));
    float M = blockmax(m, red, tid);
    if (tid == 0) { g_ys[t] = M; s_inv = 126.f / fmaxf(M, 1e-30f); }
    __syncthreads();
    float inv = s_inv;
    char4 q1v, q2v;
    quant1(v.x, inv, (int8_t&)q1v.x, (int8_t&)q2v.x);
    quant1(v.y, inv, (int8_t&)q1v.y, (int8_t&)q2v.y);
    quant1(v.z, inv, (int8_t&)q1v.z, (int8_t&)q2v.z);
    quant1(v.w, inv, (int8_t&)q1v.w, (int8_t&)q2v.w);
    ((char4*)g_yq1)[(size_t)t * 256 + tid] = q1v;
    ((char4*)g_yq2)[(size_t)t * 256 + tid] = q2v;
}

__global__ void k_loss(float* out, int out_size) {
    if (out_size <= N_TOK * NC_DIM) return;
    if (threadIdx.x == 0 && blockIdx.x == 0) {
        float s = 0.f;
        for (int e = 0; e < E_NUM; e++)
            s += ((float)g_count[e] / (float)N_TOK) * (g_probsum[e] / (float)N_TOK);
        out[(size_t)N_TOK * NC_DIM] = s * (float)E_NUM;
    }
}

// ---------------- int8 2-slice GEMM: CTA 128x128, BK=128, 2-stage ----------
// C = sA*sB/126^2 * (A1B1 + (A1B2+A2B1)/254) + bias
#define OFF_A2 16384
#define OFF_B1 32768
#define OFF_B2 49152
#define STGB 65536
#define GEMM_SMEM (1536 + 2*STGB + 128)
#define INV126SQ 6.29882827e-5f
#define RC254 0.003937007874f

__device__ __forceinline__ float gelu_fast(float v) {
    float u = 0.7978845608028654f * (v + 0.044715f * v * v * v);
    float t;
    asm("tanh.approx.f32 %0, %1;" : "=f"(t) : "f"(u));
    return 0.5f * v * (1.f + t);
}
__device__ __forceinline__ uint32_t swz(int row, int c) {
    return (uint32_t)(row * 128 + ((c ^ (row & 7)) << 4));
}

template <int MODE>
__global__ void __launch_bounds__(256, 1) k_qgemm(
    const int8_t* __restrict__ Aq1, const int8_t* __restrict__ Aq2,
    const float* __restrict__ As_, size_t sAq, size_t sAs,
    const int8_t* __restrict__ Bq1, const int8_t* __restrict__ Bq2,
    const float* __restrict__ Bs_, size_t sBq, size_t sBs,
    const float* __restrict__ bias, int sBiasE,
    float* __restrict__ out0, size_t sCe, int K, int ldc, int colmax)
{
    int e = blockIdx.z;
    int m0 = blockIdx.y * 128, n0 = blockIdx.x * 128;
    if (MODE < 2) {
        int c = g_count[e]; if (c > CAP) c = CAP;
        if (m0 >= c) return;
    }
    Aq1 += (size_t)e * sAq; Aq2 += (size_t)e * sAq; As_ += (size_t)e * sAs;
    Bq1 += (size_t)e * sBq; Bq2 += (size_t)e * sBq; Bs_ += (size_t)e * sBs;
    bias += (size_t)e * sBiasE;

    extern __shared__ char smem_raw[];
    uint32_t sbase = (smem_u32(smem_raw) + 127) & ~127u;
    float* sA = (float*)(smem_raw + (sbase - smem_u32(smem_raw)));
    float* sB = sA + 128;
    float* sbias = sA + 256;
    uint32_t stg0 = sbase + 1536;

    int tid = threadIdx.x, lane = tid & 31, wid = tid >> 5;
    int wm = (wid >> 1) * 32, wn = (wid & 1) * 64;

    if (tid < 128) {
        sA[tid] = As_[m0 + tid];
        sB[tid] = Bs_[n0 + tid];
        sbias[tid] = (n0 + tid < colmax) ? bias[n0 + tid] : 0.f;
    }

    int mainA[2][8][4], corrA[2][8][4];
#pragma unroll
    for (int i = 0; i < 2; i++)
#pragma unroll
        for (int j = 0; j < 8; j++)
#pragma unroll
            for (int q = 0; q < 4; q++) { mainA[i][j][q] = 0; corrA[i][j][q] = 0; }

    int nch = K >> 7;

    auto load_a = [&](int s, int c) {
        if (c >= nch) return;
        uint32_t stg = stg0 + s * STGB;
        int k0 = c << 7;
#pragma unroll
        for (int it = 0; it < 4; it++) {
            int i = tid + it * 256;
            int row = i >> 3, u = i & 7;
            uint32_t o = swz(row, u);
            size_t gi = (size_t)(m0 + row) * K + k0 + u * 16;
            cpa(stg + o, Aq1 + gi);
            cpa(stg + OFF_A2 + o, Aq2 + gi);
        }
    };
    auto load_b = [&](int s, int c) {
        if (c >= nch) return;
        uint32_t stg = stg0 + s * STGB;
        int k0 = c << 7;
#pragma unroll
        for (int it = 0; it < 4; it++) {
            int i = tid + it * 256;
            int row = i >> 3, u = i & 7;
            uint32_t o = swz(row, u);
            size_t gi = (size_t)(n0 + row) * K + k0 + u * 16;
            cpa(stg + OFF_B1 + o, Bq1 + gi);
            cpa(stg + OFF_B2 + o, Bq2 + gi);
        }
    };

    auto compute_ks = [&](int ks, uint32_t stg) {
        uint32_t a1[2][4], a2[2][4];
        int ar = wm + (lane & 15);
        int ac = ks * 2 + (lane >> 4);
#pragma unroll
        for (int i = 0; i < 2; i++) {
            uint32_t adr = stg + swz(ar + i * 16, ac);
            ldsm4(a1[i], adr);
            ldsm4(a2[i], adr + OFF_A2);
        }
        int jj = lane >> 4;
        int brr = wn + (lane & 7);
        int bcc = ks * 2 + ((lane >> 3) & 1);
#pragma unroll
        for (int j2 = 0; j2 < 4; j2++) {
            uint32_t b1[4], b2[4];
            uint32_t adr = stg + OFF_B1 + swz(brr + (j2 * 2 + jj) * 8, bcc);
            ldsm4(b1, adr);
            ldsm4(b2, adr + 16384);
            int ja = j2 * 2, jb = ja + 1;
#pragma unroll
            for (int i = 0; i < 2; i++) mma_s8(mainA[i][ja], a1[i], b1 + 0);
#pragma unroll
            for (int i = 0; i < 2; i++) mma_s8(mainA[i][jb], a1[i], b1 + 2);
#pragma unroll
            for (int i = 0; i < 2; i++) mma_s8(corrA[i][ja], a1[i], b2 + 0);
#pragma unroll
            for (int i = 0; i < 2; i++) mma_s8(corrA[i][jb], a1[i], b2 + 2);
#pragma unroll
            for (int i = 0; i < 2; i++) mma_s8(corrA[i][ja], a2[i], b1 + 0);
#pragma unroll
            for (int i = 0; i < 2; i++) mma_s8(corrA[i][jb], a2[i], b1 + 2);
        }
    };

    load_a(0, 0); load_b(0, 0); cpa_commit();

    for (int c = 0; c < nch; c++) {
        int s = c & 1;
        uint32_t stg = stg0 + s * STGB;
        cpa_wait<0>();
        __syncthreads();
        compute_ks(0, stg);
        load_a(s ^ 1, c + 1);
        compute_ks(1, stg);
        load_b(s ^ 1, c + 1);
        cpa_commit();
        compute_ks(2, stg);
        compute_ks(3, stg);
    }

    // epilogue
#pragma unroll
    for (int i = 0; i < 2; i++)
#pragma unroll
        for (int j = 0; j < 8; j++) {
            int rl0 = wm + i * 16 + (lane >> 2);
            int cl = wn + j * 8 + (lane & 3) * 2;
            float sb0 = sB[cl] * INV126SQ, sb1 = sB[cl + 1] * INV126SQ;
            float bz0 = sbias[cl], bz1 = sbias[cl + 1];
#pragma unroll
            for (int h = 0; h < 2; h++) {
                int rl = rl0 + h * 8;
                float sa = sA[rl];
                float f0 = ((float)mainA[i][j][h * 2 + 0] +
                            (float)corrA[i][j][h * 2 + 0] * RC254) * sa * sb0 + bz0;
                float f1 = ((float)mainA[i][j][h * 2 + 1] +
                            (float)corrA[i][j][h * 2 + 1] * RC254) * sa * sb1 + bz1;
                int row = m0 + rl, col = n0 + cl;
                if (MODE == 0) {
                    f0 = gelu_fast(f0); f1 = gelu_fast(f1);
                    *(float2*)(out0 + (size_t)e * sCe + (size_t)row * ldc + col) =
                        make_float2(f0, f1);
                } else if (MODE == 1) {
                    *(float2*)(out0 + (size_t)e * sCe + (size_t)row * ldc + col) =
                        make_float2(f0, f1);
                } else {
                    size_t oo = (size_t)row * ldc + col;
                    if (col < colmax)     out0[oo] = f0;
                    if (col + 1 < colmax) out0[oo + 1] = f1;
                }
            }
        }
}

// ---------------- launch ----------------
extern "C" void kernel_launch(void* const* d_in, const int* in_sizes, int n_in,
                              void* d_out, int out_size) {
    const float* x  = (const float*)d_in[0];
    const float* Wg = (const float*)d_in[1];
    const float* W1 = (const float*)d_in[2];
    const float* b1 = (const float*)d_in[3];
    const float* W2 = (const float*)d_in[4];
    const float* b2 = (const float*)d_in[5];
    const float* Wl = (const float*)d_in[6];
    const float* bl = (const float*)d_in[7];
    float* out = (float*)d_out;

    static int smem_set = 0;
    if (!smem_set) {
        cudaFuncSetAttribute((const void*)k_qgemm<0>, cudaFuncAttributeMaxDynamicSharedMemorySize, GEMM_SMEM);
        cudaFuncSetAttribute((const void*)k_qgemm<1>, cudaFuncAttributeMaxDynamicSharedMemorySize, GEMM_SMEM);
        cudaFuncSetAttribute((const void*)k_qgemm<2>, cudaFuncAttributeMaxDynamicSharedMemorySize, GEMM_SMEM);
        smem_set = 1;
    }

    int8_t *dq1, *dq2, *w1q1, *w1q2, *w2q1, *w2q2, *wlq1, *wlq2, *hq1, *hq2, *yq1, *yq2;
    float *ds, *w1m, *w2m, *wlm, *hs, *ys, *hbuf, *oute;
    cudaGetSymbolAddress((void**)&dq1, g_dq1);   cudaGetSymbolAddress((void**)&dq2, g_dq2);
    cudaGetSymbolAddress((void**)&ds, g_ds);
    cudaGetSymbolAddress((void**)&w1q1, g_w1q1); cudaGetSymbolAddress((void**)&w1q2, g_w1q2);
    cudaGetSymbolAddress((void**)&w1m, g_w1m);
    cudaGetSymbolAddress((void**)&w2q1, g_w2q1); cudaGetSymbolAddress((void**)&w2q2, g_w2q2);
    cudaGetSymbolAddress((void**)&w2m, g_w2m);
    cudaGetSymbolAddress((void**)&wlq1, g_wlq1); cudaGetSymbolAddress((void**)&wlq2, g_wlq2);
    cudaGetSymbolAddress((void**)&wlm, g_wlm);
    cudaGetSymbolAddress((void**)&hq1, g_hq1);   cudaGetSymbolAddress((void**)&hq2, g_hq2);
    cudaGetSymbolAddress((void**)&hs, g_hs);
    cudaGetSymbolAddress((void**)&yq1, g_yq1);   cudaGetSymbolAddress((void**)&yq2, g_yq2);
    cudaGetSymbolAddress((void**)&ys, g_ys);
    cudaGetSymbolAddress((void**)&hbuf, g_h);
    cudaGetSymbolAddress((void**)&oute, g_oute);

    k_gate<<<NB_GATE, 256>>>(x, Wg);
    k_scan<<<E_NUM, 256>>>();
    k_cmax<<<2064, 256>>>(W1, W2, Wl);
    k_big<<<BIG_TOT, 256>>>(x, W1, W2, Wl);

    // FFN1: [CAP,1024]q x [4096,1024]q^T -> g_h f32 (gelu)
    k_qgemm<0><<<dim3(H_DIM/128, CAP/128, E_NUM), 256, GEMM_SMEM>>>(
        dq1, dq2, ds, (size_t)CAP*D_DIM, CAP,
        w1q1, w1q2, w1m, (size_t)H_DIM*D_DIM, H_DIM,
        b1, H_DIM, hbuf, (size_t)CAP*H_DIM, D_DIM, H_DIM, H_DIM);

    k_hquant<<<E_NUM*CAP, 256>>>();

    // FFN2: [CAP,4096]q x [1024,4096]q^T -> oute f32
    k_qgemm<1><<<dim3(D_DIM/128, CAP/128, E_NUM), 256, GEMM_SMEM>>>(
        hq1, hq2, hs, (size_t)CAP*H_DIM, CAP,
        w2q1, w2q2, w2m, (size_t)D_DIM*H_DIM, D_DIM,
        b2, D_DIM, oute, (size_t)CAP*D_DIM, H_DIM, D_DIM, D_DIM);

    k_combine<<<N_TOK, 256>>>();

    // classifier: [16384,1024]q x [1024,1024]q^T -> out [16384,1000]
    k_qgemm<2><<<dim3(1024/128, N_TOK/128, 1), 256, GEMM_SMEM>>>(
        yq1, yq2, ys, 0, 0,
        wlq1, wlq2, wlm, 0, 0,
        bl, 0, out, 0, D_DIM, NC_DIM, NC_DIM);

    k_loss<<<1, 32>>>(out, out_size);
}

// round 10
// speedup vs baseline: 2.8286x; 2.8286x over previous
#include <cuda_runtime.h>
#include <cuda_bf16.h>
#include <math.h>
#include <stdint.h>

#define N_TOK 16384
#define D_DIM 1024
#define E_NUM 16
#define H_DIM 4096
#define NC_DIM 1000
#define CAP 2048
#define NB_GATE (N_TOK/8)

typedef __nv_bfloat16 bf16;

// ---------------- device scratch ----------------
__device__ __align__(16) bf16 g_disp_hi[(size_t)E_NUM*CAP*D_DIM];
__device__ __align__(16) bf16 g_disp_lo[(size_t)E_NUM*CAP*D_DIM];
__device__ __align__(16) bf16 g_h_hi[(size_t)E_NUM*CAP*H_DIM];
__device__ __align__(16) bf16 g_h_lo[(size_t)E_NUM*CAP*H_DIM];
__device__ __align__(16) bf16 g_y_hi[(size_t)N_TOK*D_DIM];
__device__ __align__(16) bf16 g_y_lo[(size_t)N_TOK*D_DIM];
__device__ __align__(16) bf16 g_w1t_hi[(size_t)E_NUM*H_DIM*D_DIM];
__device__ __align__(16) bf16 g_w1t_lo[(size_t)E_NUM*H_DIM*D_DIM];
__device__ __align__(16) bf16 g_w2t_hi[(size_t)E_NUM*D_DIM*H_DIM];
__device__ __align__(16) bf16 g_w2t_lo[(size_t)E_NUM*D_DIM*H_DIM];
__device__ __align__(16) bf16 g_wlt_hi[(size_t)1024*D_DIM];
__device__ __align__(16) bf16 g_wlt_lo[(size_t)1024*D_DIM];
__device__ int   g_idx[N_TOK];
__device__ float g_gate[N_TOK];
__device__ int   g_lrank[N_TOK];
__device__ int   g_bhist[NB_GATE][E_NUM];
__device__ float g_bprob[NB_GATE][E_NUM];
__device__ int   g_boff[NB_GATE][E_NUM];
__device__ int   g_count[E_NUM];
__device__ float g_probsum[E_NUM];
__device__ int   g_inv[E_NUM*CAP];

// ---------------- PTX helpers ----------------
__device__ __forceinline__ uint32_t smem_u32(const void* p) {
    return (uint32_t)__cvta_generic_to_shared(p);
}
__device__ __forceinline__ void cpa(uint32_t dst, const void* src) {
    asm volatile("cp.async.cg.shared.global [%0], [%1], 16;" :: "r"(dst), "l"(src) : "memory");
}
__device__ __forceinline__ void cpa_commit() { asm volatile("cp.async.commit_group;" ::: "memory"); }
template<int N> __device__ __forceinline__ void cpa_wait() {
    asm volatile("cp.async.wait_group %0;" :: "n"(N) : "memory");
}
__device__ __forceinline__ void ldsm4(uint32_t* r, uint32_t a) {
    asm volatile("ldmatrix.sync.aligned.m8n8.x4.shared.b16 {%0,%1,%2,%3}, [%4];"
                 : "=r"(r[0]), "=r"(r[1]), "=r"(r[2]), "=r"(r[3]) : "r"(a));
}
__device__ __forceinline__ void mma_bf16(float* d, const uint32_t* a, const uint32_t* b) {
    asm volatile(
        "mma.sync.aligned.m16n8k16.row.col.f32.bf16.bf16.f32 "
        "{%0,%1,%2,%3}, {%4,%5,%6,%7}, {%8,%9}, {%0,%1,%2,%3};"
        : "+f"(d[0]), "+f"(d[1]), "+f"(d[2]), "+f"(d[3])
        : "r"(a[0]), "r"(a[1]), "r"(a[2]), "r"(a[3]), "r"(b[0]), "r"(b[1]));
}

// packed hi/lo split: 2 floats -> bf16x2 hi + bf16x2 lo
__device__ __forceinline__ void split2(float a, float b, bf16* hi, bf16* lo) {
    __nv_bfloat162 h = __float22bfloat162_rn(make_float2(a, b));
    *(__nv_bfloat162*)hi = h;
    float2 hf = __bfloat1622float2(h);
    *(__nv_bfloat162*)lo = __float22bfloat162_rn(make_float2(a - hf.x, b - hf.y));
}

// ---------------- gating ----------------
__global__ void k_gate(const float* __restrict__ x, const float* __restrict__ Wg) {
    int warp = threadIdx.x >> 5, lane = threadIdx.x & 31;
    int t = blockIdx.x * 8 + warp;
    __shared__ float s_prob[E_NUM];
    __shared__ int s_idx[8];
    if (threadIdx.x < E_NUM) s_prob[threadIdx.x] = 0.f;
    __syncthreads();
    float acc[E_NUM];
#pragma unroll
    for (int e = 0; e < E_NUM; e++) acc[e] = 0.f;
    const float* xr = x + (size_t)t * D_DIM;
    for (int j = 0; j < D_DIM / 32; j++) {
        float xv = xr[lane + 32 * j];
        const float* wr = Wg + (size_t)(lane + 32 * j) * E_NUM;
#pragma unroll
        for (int e = 0; e < E_NUM; e++) acc[e] = fmaf(xv, __ldg(wr + e), acc[e]);
    }
#pragma unroll
    for (int e = 0; e < E_NUM; e++)
#pragma unroll
        for (int o = 16; o > 0; o >>= 1) acc[e] += __shfl_xor_sync(0xffffffffu, acc[e], o);
    if (lane == 0) {
        float m = acc[0]; int ai = 0;
#pragma unroll
        for (int e = 1; e < E_NUM; e++) if (acc[e] > m) { m = acc[e]; ai = e; }
        float p[E_NUM]; float s = 0.f;
#pragma unroll
        for (int e = 0; e < E_NUM; e++) { p[e] = expf(acc[e] - m); s += p[e]; }
        float inv = 1.f / s;
#pragma unroll
        for (int e = 0; e < E_NUM; e++) atomicAdd(&s_prob[e], p[e] * inv);
        g_idx[t] = ai; g_gate[t] = p[ai] * inv; s_idx[warp] = ai;
    }
    __syncthreads();
    if (threadIdx.x == 0) {
        int cnt[E_NUM];
#pragma unroll
        for (int e = 0; e < E_NUM; e++) cnt[e] = 0;
#pragma unroll
        for (int w = 0; w < 8; w++) {
            int e = s_idx[w];
            g_lrank[blockIdx.x * 8 + w] = cnt[e];
            cnt[e]++;
        }
#pragma unroll
        for (int e = 0; e < E_NUM; e++) g_bhist[blockIdx.x][e] = cnt[e];
    }
    if (threadIdx.x < E_NUM) g_bprob[blockIdx.x][threadIdx.x] = s_prob[threadIdx.x];
}

// ---------------- scan + probsum reduce + pad ----------------
__global__ void k_scan() {
    const int PB = NB_GATE / 256;
    int e = blockIdx.x, tid = threadIdx.x;
    int v[PB]; int s = 0;
    float ps = 0.f;
#pragma unroll
    for (int i = 0; i < PB; i++) {
        v[i] = g_bhist[tid * PB + i][e];
        s += v[i];
        ps += g_bprob[tid * PB + i][e];
    }
    __shared__ int sh[256];
    __shared__ float sp[256];
    sh[tid] = s; sp[tid] = ps;
    __syncthreads();
    for (int o = 1; o < 256; o <<= 1) {
        int q = (tid >= o) ? sh[tid - o] : 0;
        __syncthreads(); sh[tid] += q; __syncthreads();
    }
    int off = sh[tid] - s;
#pragma unroll
    for (int i = 0; i < PB; i++) { g_boff[tid * PB + i][e] = off; off += v[i]; }
    for (int o = 128; o > 0; o >>= 1) {
        if (tid < o) sp[tid] += sp[tid + o];
        __syncthreads();
    }
    if (tid == 0) { g_count[e] = sh[255]; g_probsum[e] = sp[0]; }
    __syncthreads();
    // pad rows [count, round128(count)): zero A operand, mark inv = -1
    int c = sh[255]; if (c > CAP) c = CAP;
    int r1 = (c + 127) & ~127; if (r1 > CAP) r1 = CAP;
    for (int r = c; r < r1; r++) {
        size_t b = ((size_t)e * CAP + r) * D_DIM + tid * 4;
        *(float2*)(g_disp_hi + b) = make_float2(0.f, 0.f);
        *(float2*)(g_disp_lo + b) = make_float2(0.f, 0.f);
    }
    for (int r = c + tid; r < r1; r += 256) g_inv[e * CAP + r] = -1;
}

// wsplit body: in [E,R,C] fp32 -> out [E,Cpad,R] bf16 hi/lo
__device__ __forceinline__ void wsplit_body(
    const float* __restrict__ in, bf16* __restrict__ ohi, bf16* __restrict__ olo,
    int R, int C, int Cpad, int bx, int by, int bz, int tid)
{
    __shared__ float s[32][33];
    const float* ip = in + (size_t)bz * R * C;
    size_t ob = (size_t)bz * Cpad * R;
    int c0 = bx * 32, r0 = by * 32;
    int tx = tid & 31, ty = tid >> 5;
#pragma unroll
    for (int k = 0; k < 4; k++) {
        int r = r0 + ty + 8 * k, c = c0 + tx;
        s[ty + 8 * k][tx] = (c < C) ? ip[(size_t)r * C + c] : 0.f;
    }
    __syncthreads();
#pragma unroll
    for (int k = 0; k < 4; k++) {
        int cc = ty + 8 * k;
        float v = s[tx][cc];
        bf16 h = __float2bfloat16(v);
        size_t o = ob + (size_t)(c0 + cc) * R + r0 + tx;
        ohi[o] = h;
        olo[o] = __float2bfloat16(v - __bfloat162float(h));
    }
}

#define BIG_W1 16384
#define BIG_W2 (16384 + 65536)
#define BIG_WL (16384 + 2*65536)
#define BIG_TOT (16384 + 2*65536 + 1024)

__global__ void k_big(const float* __restrict__ x, const float* __restrict__ W1,
                      const float* __restrict__ W2, const float* __restrict__ Wl) {
    int b = blockIdx.x, tid = threadIdx.x;
    if (b < BIG_W1) {
        int t = b;
        int e = g_idx[t];
        int pos = g_boff[t >> 3][e] + g_lrank[t];
        if (pos < CAP) {
            if (tid == 0) g_inv[e * CAP + pos] = t;
            float4 v = ((const float4*)(x + (size_t)t * D_DIM))[tid];
            size_t o = ((size_t)e * CAP + pos) * D_DIM + tid * 4;
            split2(v.x, v.y, g_disp_hi + o, g_disp_lo + o);
            split2(v.z, v.w, g_disp_hi + o + 2, g_disp_lo + o + 2);
        } else {
            // dropped token: y = 0
            size_t o = (size_t)t * D_DIM + tid * 4;
            *(float2*)(g_y_hi + o) = make_float2(0.f, 0.f);
            *(float2*)(g_y_lo + o) = make_float2(0.f, 0.f);
        }
    } else if (b < BIG_W2) {
        int i = b - BIG_W1;
        int bx = i % 128, by = (i / 128) % 32, bz = i / (128 * 32);
        wsplit_body(W1, g_w1t_hi, g_w1t_lo, D_DIM, H_DIM, H_DIM, bx, by, bz, tid);
    } else if (b < BIG_WL) {
        int i = b - BIG_W2;
        int bx = i % 32, by = (i / 32) % 128, bz = i / (32 * 128);
        wsplit_body(W2, g_w2t_hi, g_w2t_lo, H_DIM, D_DIM, D_DIM, bx, by, bz, tid);
    } else {
        int i = b - BIG_WL;
        int bx = i % 32, by = i / 32;
        wsplit_body(Wl, g_wlt_hi, g_wlt_lo, D_DIM, NC_DIM, 1024, bx, by, 0, tid);
    }
}

__global__ void k_loss(float* out, int out_size) {
    if (out_size <= N_TOK * NC_DIM) return;
    if (threadIdx.x == 0 && blockIdx.x == 0) {
        float s = 0.f;
        for (int e = 0; e < E_NUM; e++)
            s += ((float)g_count[e] / (float)N_TOK) * (g_probsum[e] / (float)N_TOK);
        out[(size_t)N_TOK * NC_DIM] = s * (float)E_NUM;
    }
}

// ------------- mma.sync bf16 GEMM: CTA 128xNT, BK=64, 2-stage, 1 sync/chunk
// WI=4: NT=256, 8 warps 2x4, warp 64x64.  WI=2: NT=128, 8 warps 4x2, warp 32x64.
// MODE 0: FFN1 -> h bf16 hi/lo (bias+gelu)
// MODE 1: FFN2 -> y bf16 hi/lo at token rows via g_inv ((acc+bias)*gate)
// MODE 2: classifier -> f32 out, col < colmax
#define OFF_ALO 16384
#define OFF_BHI 32768

__device__ __forceinline__ float gelu_fast(float v) {
    float u = 0.7978845608028654f * (v + 0.044715f * v * v * v);
    float t;
    asm("tanh.approx.f32 %0, %1;" : "=f"(t) : "f"(u));
    return 0.5f * v * (1.f + t);
}
__device__ __forceinline__ uint32_t swz(int row, int c) {
    return (uint32_t)(row * 128 + ((c ^ (row & 7)) << 4));
}

template <int MODE, int WI>
__global__ void __launch_bounds__(256, 1) k_mgemm(
    const bf16* __restrict__ Ahi, const bf16* __restrict__ Alo, size_t sAe,
    const bf16* __restrict__ Bhi, const bf16* __restrict__ Blo, size_t sBe,
    const float* __restrict__ bias, int sBiasE,
    void* __restrict__ out0, void* __restrict__ out1, size_t sCe,
    int K, int ldc, int colmax)
{
    constexpr int NT = WI * 64;
    constexpr int STGB = OFF_BHI + 2 * NT * 128;

    int e = blockIdx.z;
    int m0 = blockIdx.y * 128, n0 = blockIdx.x * NT;
    if (MODE < 2) {
        int c = g_count[e]; if (c > CAP) c = CAP;
        if (m0 >= c) return;
    }
    Ahi += (size_t)e * sAe; Alo += (size_t)e * sAe;
    Bhi += (size_t)e * sBe; Blo += (size_t)e * sBe;
    bias += (size_t)e * sBiasE;

    extern __shared__ char smem_raw[];
    uint32_t base = (smem_u32(smem_raw) + 127) & ~127u;

    int tid = threadIdx.x, lane = tid & 31, wid = tid >> 5;
    int wm, wn;
    if (WI == 4) { wm = (wid >> 2) * 64; wn = (wid & 3) * 64; }
    else         { wm = (wid >> 1) * 32; wn = (wid & 1) * 64; }

    float acc[WI][8][4];
#pragma unroll
    for (int i = 0; i < WI; i++)
#pragma unroll
        for (int j = 0; j < 8; j++)
#pragma unroll
            for (int q = 0; q < 4; q++) acc[i][j][q] = 0.f;

    int nch = K >> 6;

    auto load_a = [&](int s, int c) {
        if (c >= nch) return;
        uint32_t stg = base + s * STGB;
        int k0 = c << 6;
#pragma unroll
        for (int it = 0; it < 4; it++) {
            int i = tid + it * 256;
            int row = i >> 3, cc = i & 7;
            uint32_t o = swz(row, cc);
            size_t gi = (size_t)(m0 + row) * K + k0 + cc * 8;
            cpa(stg + o, Ahi + gi);
            cpa(stg + OFF_ALO + o, Alo + gi);
        }
    };
    auto load_bh = [&](int s, int c) {
        if (c >= nch) return;
        uint32_t stg = base + s * STGB;
        int k0 = c << 6;
#pragma unroll
        for (int it = 0; it < NT / 32; it++) {
            int i = tid + it * 256;
            int row = i >> 3, cc = i & 7;
            size_t gi = (size_t)(n0 + row) * K + k0 + cc * 8;
            cpa(stg + OFF_BHI + swz(row, cc), Bhi + gi);
        }
    };
    auto load_bl = [&](int s, int c) {
        if (c >= nch) return;
        uint32_t stg = base + s * STGB;
        int k0 = c << 6;
#pragma unroll
        for (int it = 0; it < NT / 32; it++) {
            int i = tid + it * 256;
            int row = i >> 3, cc = i & 7;
            size_t gi = (size_t)(n0 + row) * K + k0 + cc * 8;
            cpa(stg + OFF_BHI + NT * 128 + swz(row, cc), Blo + gi);
        }
    };

    auto compute_ks = [&](int ks, uint32_t stg) {
        uint32_t ah[WI][4], al[WI][4];
        int ar = wm + (lane & 15);
        int ac = ks * 2 + (lane >> 4);
#pragma unroll
        for (int i = 0; i < WI; i++) {
            uint32_t adr = stg + swz(ar + i * 16, ac);
            ldsm4(ah[i], adr);
            ldsm4(al[i], adr + OFF_ALO);
        }
        int jj = (lane >> 4);
        int brr = wn + (lane & 7);
        int bcc = ks * 2 + ((lane >> 3) & 1);
#pragma unroll
        for (int j2 = 0; j2 < 4; j2++) {
            uint32_t bh[4], bl[4];
            uint32_t adr = stg + OFF_BHI + swz(brr + (j2 * 2 + jj) * 8, bcc);
            ldsm4(bh, adr);
            ldsm4(bl, adr + NT * 128);
            int ja = j2 * 2, jb = ja + 1;
#pragma unroll
            for (int i = 0; i < WI; i++) mma_bf16(acc[i][ja], ah[i], bh + 0);
#pragma unroll
            for (int i = 0; i < WI; i++) mma_bf16(acc[i][jb], ah[i], bh + 2);
#pragma unroll
            for (int i = 0; i < WI; i++) mma_bf16(acc[i][ja], ah[i], bl + 0);
#pragma unroll
            for (int i = 0; i < WI; i++) mma_bf16(acc[i][jb], ah[i], bl + 2);
#pragma unroll
            for (int i = 0; i < WI; i++) mma_bf16(acc[i][ja], al[i], bh + 0);
#pragma unroll
            for (int i = 0; i < WI; i++) mma_bf16(acc[i][jb], al[i], bh + 2);
        }
    };

    load_a(0, 0); load_bh(0, 0); load_bl(0, 0); cpa_commit();

    for (int c = 0; c < nch; c++) {
        int s = c & 1;
        uint32_t stg = base + s * STGB;
        cpa_wait<0>();
        __syncthreads();
        compute_ks(0, stg);
        load_a(s ^ 1, c + 1);
        load_bh(s ^ 1, c + 1);
        compute_ks(1, stg);
        load_bl(s ^ 1, c + 1);
        cpa_commit();
        compute_ks(2, stg);
        compute_ks(3, stg);
    }

    int rb = m0 + wm, cb = n0 + wn;
#pragma unroll
    for (int i = 0; i < WI; i++)
#pragma unroll
        for (int j = 0; j < 8; j++) {
            int r0 = rb + i * 16 + (lane >> 2);
            int c0 = cb + j * 8 + (lane & 3) * 2;
            float bx = bias[c0], by = bias[c0 + 1];
#pragma unroll
            for (int h = 0; h < 2; h++) {
                int row = r0 + h * 8;
                float v0 = acc[i][j][h * 2 + 0] + bx;
                float v1 = acc[i][j][h * 2 + 1] + by;
                if (MODE == 0) {
                    size_t o = (size_t)e * sCe + (size_t)row * ldc + c0;
                    v0 = gelu_fast(v0); v1 = gelu_fast(v1);
                    split2(v0, v1, (bf16*)out0 + o, (bf16*)out1 + o);
                } else if (MODE == 1) {
                    int t = g_inv[e * CAP + row];
                    if (t >= 0) {
                        float g = g_gate[t];
                        size_t o = (size_t)t * ldc + c0;
                        split2(v0 * g, v1 * g, (bf16*)out0 + o, (bf16*)out1 + o);
                    }
                } else {
                    size_t oo = (size_t)row * ldc + c0;
                    if (c0 < colmax)     ((float*)out0)[oo] = v0;
                    if (c0 + 1 < colmax) ((float*)out0)[oo + 1] = v1;
                }
            }
        }
}

// ---------------- launch ----------------
extern "C" void kernel_launch(void* const* d_in, const int* in_sizes, int n_in,
                              void* d_out, int out_size) {
    const float* x  = (const float*)d_in[0];
    const float* Wg = (const float*)d_in[1];
    const float* W1 = (const float*)d_in[2];
    const float* b1 = (const float*)d_in[3];
    const float* W2 = (const float*)d_in[4];
    const float* b2 = (const float*)d_in[5];
    const float* Wl = (const float*)d_in[6];
    const float* bl = (const float*)d_in[7];
    float* out = (float*)d_out;

    const int GEMM_SMEM4 = 2 * (32768 + 2 * 256 * 128) + 128;  // 196736
    const int GEMM_SMEM2 = 2 * (32768 + 2 * 128 * 128) + 128;  // 131200

    static int smem_set = 0;
    if (!smem_set) {
        cudaFuncSetAttribute((const void*)k_mgemm<0,4>, cudaFuncAttributeMaxDynamicSharedMemorySize, GEMM_SMEM4);
        cudaFuncSetAttribute((const void*)k_mgemm<1,4>, cudaFuncAttributeMaxDynamicSharedMemorySize, GEMM_SMEM4);
        cudaFuncSetAttribute((const void*)k_mgemm<2,2>, cudaFuncAttributeMaxDynamicSharedMemorySize, GEMM_SMEM2);
        smem_set = 1;
    }

    bf16 *w1h, *w1l, *w2h, *w2l, *wlh, *wll, *dh, *dl, *hh, *hl, *yh, *yl;
    cudaGetSymbolAddress((void**)&w1h, g_w1t_hi); cudaGetSymbolAddress((void**)&w1l, g_w1t_lo);
    cudaGetSymbolAddress((void**)&w2h, g_w2t_hi); cudaGetSymbolAddress((void**)&w2l, g_w2t_lo);
    cudaGetSymbolAddress((void**)&wlh, g_wlt_hi); cudaGetSymbolAddress((void**)&wll, g_wlt_lo);
    cudaGetSymbolAddress((void**)&dh, g_disp_hi); cudaGetSymbolAddress((void**)&dl, g_disp_lo);
    cudaGetSymbolAddress((void**)&hh, g_h_hi);    cudaGetSymbolAddress((void**)&hl, g_h_lo);
    cudaGetSymbolAddress((void**)&yh, g_y_hi);    cudaGetSymbolAddress((void**)&yl, g_y_lo);

    k_gate<<<NB_GATE, 256>>>(x, Wg);
    k_scan<<<E_NUM, 256>>>();
    k_big<<<BIG_TOT, 256>>>(x, W1, W2, Wl);

    // FFN1: [CAP,1024] x [4096,1024]^T -> h bf16 hi/lo (bias+gelu)
    k_mgemm<0,4><<<dim3(H_DIM/256, CAP/128, E_NUM), 256, GEMM_SMEM4>>>(
        dh, dl, (size_t)CAP*D_DIM, w1h, w1l, (size_t)H_DIM*D_DIM,
        b1, H_DIM, hh, hl, (size_t)CAP*H_DIM, D_DIM, H_DIM, H_DIM);
    // FFN2: [CAP,4096] x [1024,4096]^T -> y bf16 hi/lo at token rows (fused combine)
    k_mgemm<1,4><<<dim3(D_DIM/256, CAP/128, E_NUM), 256, GEMM_SMEM4>>>(
        hh, hl, (size_t)CAP*H_DIM, w2h, w2l, (size_t)D_DIM*H_DIM,
        b2, D_DIM, yh, yl, 0, H_DIM, D_DIM, D_DIM);

    // classifier (NT=128): [16384,1024] x [1024,1024]^T -> out [16384,1000]
    k_mgemm<2,2><<<dim3(1024/128, N_TOK/128, 1), 256, GEMM_SMEM2>>>(
        yh, yl, 0, wlh, wll, 0,
        bl, 0, out, nullptr, 0, D_DIM, NC_DIM, NC_DIM);

    k_loss<<<1, 32>>>(out, out_size);
}

// round 11
// speedup vs baseline: 2.8312x; 1.0009x over previous
#include <cuda_runtime.h>
#include <cuda_bf16.h>
#include <math.h>
#include <stdint.h>

#define N_TOK 16384
#define D_DIM 1024
#define E_NUM 16
#define H_DIM 4096
#define NC_DIM 1000
#define CAP 2048
#define NB_GATE (N_TOK/8)

typedef __nv_bfloat16 bf16;

// ---------------- device scratch ----------------
__device__ __align__(16) bf16 g_disp_hi[(size_t)E_NUM*CAP*D_DIM];
__device__ __align__(16) bf16 g_disp_lo[(size_t)E_NUM*CAP*D_DIM];
__device__ __align__(16) bf16 g_h_hi[(size_t)E_NUM*CAP*H_DIM];
__device__ __align__(16) bf16 g_h_lo[(size_t)E_NUM*CAP*H_DIM];
__device__ __align__(16) bf16 g_y_hi[(size_t)N_TOK*D_DIM];
__device__ __align__(16) bf16 g_y_lo[(size_t)N_TOK*D_DIM];
__device__ __align__(16) bf16 g_w1t_hi[(size_t)E_NUM*H_DIM*D_DIM];
__device__ __align__(16) bf16 g_w1t_lo[(size_t)E_NUM*H_DIM*D_DIM];
__device__ __align__(16) bf16 g_w2t_hi[(size_t)E_NUM*D_DIM*H_DIM];
__device__ __align__(16) bf16 g_w2t_lo[(size_t)E_NUM*D_DIM*H_DIM];
__device__ __align__(16) bf16 g_wlt_hi[(size_t)1024*D_DIM];
__device__ __align__(16) bf16 g_wlt_lo[(size_t)1024*D_DIM];
__device__ int   g_idx[N_TOK];
__device__ float g_gate[N_TOK];
__device__ int   g_lrank[N_TOK];
__device__ int   g_bhist[NB_GATE][E_NUM];
__device__ float g_bprob[NB_GATE][E_NUM];
__device__ int   g_boff[NB_GATE][E_NUM];
__device__ int   g_count[E_NUM];
__device__ float g_probsum[E_NUM];
__device__ int   g_inv[E_NUM*CAP];

// ---------------- PTX helpers ----------------
__device__ __forceinline__ uint32_t smem_u32(const void* p) {
    return (uint32_t)__cvta_generic_to_shared(p);
}
__device__ __forceinline__ void cpa(uint32_t dst, const void* src) {
    asm volatile("cp.async.cg.shared.global [%0], [%1], 16;" :: "r"(dst), "l"(src) : "memory");
}
__device__ __forceinline__ void cpa_commit() { asm volatile("cp.async.commit_group;" ::: "memory"); }
template<int N> __device__ __forceinline__ void cpa_wait() {
    asm volatile("cp.async.wait_group %0;" :: "n"(N) : "memory");
}
__device__ __forceinline__ void ldsm4(uint32_t* r, uint32_t a) {
    asm volatile("ldmatrix.sync.aligned.m8n8.x4.shared.b16 {%0,%1,%2,%3}, [%4];"
                 : "=r"(r[0]), "=r"(r[1]), "=r"(r[2]), "=r"(r[3]) : "r"(a));
}
__device__ __forceinline__ void mma_bf16(float* d, const uint32_t* a, const uint32_t* b) {
    asm volatile(
        "mma.sync.aligned.m16n8k16.row.col.f32.bf16.bf16.f32 "
        "{%0,%1,%2,%3}, {%4,%5,%6,%7}, {%8,%9}, {%0,%1,%2,%3};"
        : "+f"(d[0]), "+f"(d[1]), "+f"(d[2]), "+f"(d[3])
        : "r"(a[0]), "r"(a[1]), "r"(a[2]), "r"(a[3]), "r"(b[0]), "r"(b[1]));
}

// packed hi/lo split: 2 floats -> bf16x2 hi + bf16x2 lo (as u32)
__device__ __forceinline__ void split2u(float a, float b, uint32_t& hi, uint32_t& lo) {
    __nv_bfloat162 h = __float22bfloat162_rn(make_float2(a, b));
    hi = *(uint32_t*)&h;
    float2 hf = __bfloat1622float2(h);
    __nv_bfloat162 l = __float22bfloat162_rn(make_float2(a - hf.x, b - hf.y));
    lo = *(uint32_t*)&l;
}
__device__ __forceinline__ void split2(float a, float b, bf16* hi, bf16* lo) {
    uint32_t h, l;
    split2u(a, b, h, l);
    *(uint32_t*)hi = h; *(uint32_t*)lo = l;
}

// ---------------- gating ----------------
__global__ void k_gate(const float* __restrict__ x, const float* __restrict__ Wg) {
    int warp = threadIdx.x >> 5, lane = threadIdx.x & 31;
    int t = blockIdx.x * 8 + warp;
    __shared__ float s_prob[E_NUM];
    __shared__ int s_idx[8];
    if (threadIdx.x < E_NUM) s_prob[threadIdx.x] = 0.f;
    __syncthreads();
    float acc[E_NUM];
#pragma unroll
    for (int e = 0; e < E_NUM; e++) acc[e] = 0.f;
    const float* xr = x + (size_t)t * D_DIM;
    for (int j = 0; j < D_DIM / 32; j++) {
        float xv = xr[lane + 32 * j];
        const float* wr = Wg + (size_t)(lane + 32 * j) * E_NUM;
#pragma unroll
        for (int e = 0; e < E_NUM; e++) acc[e] = fmaf(xv, __ldg(wr + e), acc[e]);
    }
#pragma unroll
    for (int e = 0; e < E_NUM; e++)
#pragma unroll
        for (int o = 16; o > 0; o >>= 1) acc[e] += __shfl_xor_sync(0xffffffffu, acc[e], o);
    if (lane == 0) {
        float m = acc[0]; int ai = 0;
#pragma unroll
        for (int e = 1; e < E_NUM; e++) if (acc[e] > m) { m = acc[e]; ai = e; }
        float p[E_NUM]; float s = 0.f;
#pragma unroll
        for (int e = 0; e < E_NUM; e++) { p[e] = expf(acc[e] - m); s += p[e]; }
        float inv = 1.f / s;
#pragma unroll
        for (int e = 0; e < E_NUM; e++) atomicAdd(&s_prob[e], p[e] * inv);
        g_idx[t] = ai; g_gate[t] = p[ai] * inv; s_idx[warp] = ai;
    }
    __syncthreads();
    if (threadIdx.x == 0) {
        int cnt[E_NUM];
#pragma unroll
        for (int e = 0; e < E_NUM; e++) cnt[e] = 0;
#pragma unroll
        for (int w = 0; w < 8; w++) {
            int e = s_idx[w];
            g_lrank[blockIdx.x * 8 + w] = cnt[e];
            cnt[e]++;
        }
#pragma unroll
        for (int e = 0; e < E_NUM; e++) g_bhist[blockIdx.x][e] = cnt[e];
    }
    if (threadIdx.x < E_NUM) g_bprob[blockIdx.x][threadIdx.x] = s_prob[threadIdx.x];
}

// ---------------- scan + probsum reduce + pad ----------------
__global__ void k_scan() {
    const int PB = NB_GATE / 256;
    int e = blockIdx.x, tid = threadIdx.x;
    int v[PB]; int s = 0;
    float ps = 0.f;
#pragma unroll
    for (int i = 0; i < PB; i++) {
        v[i] = g_bhist[tid * PB + i][e];
        s += v[i];
        ps += g_bprob[tid * PB + i][e];
    }
    __shared__ int sh[256];
    __shared__ float sp[256];
    sh[tid] = s; sp[tid] = ps;
    __syncthreads();
    for (int o = 1; o < 256; o <<= 1) {
        int q = (tid >= o) ? sh[tid - o] : 0;
        __syncthreads(); sh[tid] += q; __syncthreads();
    }
    int off = sh[tid] - s;
#pragma unroll
    for (int i = 0; i < PB; i++) { g_boff[tid * PB + i][e] = off; off += v[i]; }
    for (int o = 128; o > 0; o >>= 1) {
        if (tid < o) sp[tid] += sp[tid + o];
        __syncthreads();
    }
    if (tid == 0) { g_count[e] = sh[255]; g_probsum[e] = sp[0]; }
    __syncthreads();
    // pad rows [count, round128(count)): zero A operand, mark inv = -1
    int c = sh[255]; if (c > CAP) c = CAP;
    int r1 = (c + 127) & ~127; if (r1 > CAP) r1 = CAP;
    for (int r = c; r < r1; r++) {
        size_t b = ((size_t)e * CAP + r) * D_DIM + tid * 4;
        *(float2*)(g_disp_hi + b) = make_float2(0.f, 0.f);
        *(float2*)(g_disp_lo + b) = make_float2(0.f, 0.f);
    }
    for (int r = c + tid; r < r1; r += 256) g_inv[e * CAP + r] = -1;
}

// wsplit body: in [E,R,C] fp32 -> out [E,Cpad,R] bf16 hi/lo
// write phase: each thread owns 1 column x 4 consecutive rows -> 8B stores
__device__ __forceinline__ void wsplit_body(
    const float* __restrict__ in, bf16* __restrict__ ohi, bf16* __restrict__ olo,
    int R, int C, int Cpad, int bx, int by, int bz, int tid)
{
    __shared__ float s[32][33];
    const float* ip = in + (size_t)bz * R * C;
    size_t ob = (size_t)bz * Cpad * R;
    int c0 = bx * 32, r0 = by * 32;
    int tx = tid & 31, ty = tid >> 5;
#pragma unroll
    for (int k = 0; k < 4; k++) {
        int r = r0 + ty + 8 * k, c = c0 + tx;
        s[ty + 8 * k][tx] = (c < C) ? ip[(size_t)r * C + c] : 0.f;
    }
    __syncthreads();
    // thread -> column (tid>>3), 4 consecutive rows starting (tid&7)*4
    int cl = tid >> 3, rg = (tid & 7) * 4;
    int n = c0 + cl;
    uint32_t h01, l01, h23, l23;
    split2u(s[rg + 0][cl], s[rg + 1][cl], h01, l01);
    split2u(s[rg + 2][cl], s[rg + 3][cl], h23, l23);
    size_t o = ob + (size_t)n * R + r0 + rg;
    *(uint2*)(ohi + o) = make_uint2(h01, h23);
    *(uint2*)(olo + o) = make_uint2(l01, l23);
}

#define BIG_W1 16384
#define BIG_W2 (16384 + 65536)
#define BIG_WL (16384 + 2*65536)
#define BIG_TOT (16384 + 2*65536 + 1024)

__global__ void k_big(const float* __restrict__ x, const float* __restrict__ W1,
                      const float* __restrict__ W2, const float* __restrict__ Wl) {
    int b = blockIdx.x, tid = threadIdx.x;
    if (b < BIG_W1) {
        int t = b;
        int e = g_idx[t];
        int pos = g_boff[t >> 3][e] + g_lrank[t];
        if (pos < CAP) {
            if (tid == 0) g_inv[e * CAP + pos] = t;
            float4 v = ((const float4*)(x + (size_t)t * D_DIM))[tid];
            size_t o = ((size_t)e * CAP + pos) * D_DIM + tid * 4;
            uint32_t h01, l01, h23, l23;
            split2u(v.x, v.y, h01, l01);
            split2u(v.z, v.w, h23, l23);
            *(uint2*)(g_disp_hi + o) = make_uint2(h01, h23);
            *(uint2*)(g_disp_lo + o) = make_uint2(l01, l23);
        } else {
            size_t o = (size_t)t * D_DIM + tid * 4;
            *(float2*)(g_y_hi + o) = make_float2(0.f, 0.f);
            *(float2*)(g_y_lo + o) = make_float2(0.f, 0.f);
        }
    } else if (b < BIG_W2) {
        int i = b - BIG_W1;
        int bx = i % 128, by = (i / 128) % 32, bz = i / (128 * 32);
        wsplit_body(W1, g_w1t_hi, g_w1t_lo, D_DIM, H_DIM, H_DIM, bx, by, bz, tid);
    } else if (b < BIG_WL) {
        int i = b - BIG_W2;
        int bx = i % 32, by = (i / 32) % 128, bz = i / (32 * 128);
        wsplit_body(W2, g_w2t_hi, g_w2t_lo, H_DIM, D_DIM, D_DIM, bx, by, bz, tid);
    } else {
        int i = b - BIG_WL;
        int bx = i % 32, by = i / 32;
        wsplit_body(Wl, g_wlt_hi, g_wlt_lo, D_DIM, NC_DIM, 1024, bx, by, 0, tid);
    }
}

__global__ void k_loss(float* out, int out_size) {
    if (out_size <= N_TOK * NC_DIM) return;
    if (threadIdx.x == 0 && blockIdx.x == 0) {
        float s = 0.f;
        for (int e = 0; e < E_NUM; e++)
            s += ((float)g_count[e] / (float)N_TOK) * (g_probsum[e] / (float)N_TOK);
        out[(size_t)N_TOK * NC_DIM] = s * (float)E_NUM;
    }
}

// ------------- mma.sync bf16 GEMM: CTA 128xNT, BK=64, 2-stage, 1 sync/chunk
#define OFF_ALO 16384
#define OFF_BHI 32768

__device__ __forceinline__ float gelu_fast(float v) {
    float u = 0.7978845608028654f * (v + 0.044715f * v * v * v);
    float t;
    asm("tanh.approx.f32 %0, %1;" : "=f"(t) : "f"(u));
    return 0.5f * v * (1.f + t);
}
__device__ __forceinline__ uint32_t swz(int row, int c) {
    return (uint32_t)(row * 128 + ((c ^ (row & 7)) << 4));
}

template <int MODE, int WI>
__global__ void __launch_bounds__(256, 1) k_mgemm(
    const bf16* __restrict__ Ahi, const bf16* __restrict__ Alo, size_t sAe,
    const bf16* __restrict__ Bhi, const bf16* __restrict__ Blo, size_t sBe,
    const float* __restrict__ bias, int sBiasE,
    void* __restrict__ out0, void* __restrict__ out1, size_t sCe,
    int K, int ldc, int colmax)
{
    constexpr int NT = WI * 64;
    constexpr int STGB = OFF_BHI + 2 * NT * 128;

    int e = blockIdx.z;
    int m0 = blockIdx.y * 128, n0 = blockIdx.x * NT;
    if (MODE < 2) {
        int c = g_count[e]; if (c > CAP) c = CAP;
        if (m0 >= c) return;
    }
    Ahi += (size_t)e * sAe; Alo += (size_t)e * sAe;
    Bhi += (size_t)e * sBe; Blo += (size_t)e * sBe;
    bias += (size_t)e * sBiasE;

    extern __shared__ char smem_raw[];
    uint32_t base = (smem_u32(smem_raw) + 127) & ~127u;

    int tid = threadIdx.x, lane = tid & 31, wid = tid >> 5;
    int wm, wn;
    if (WI == 4) { wm = (wid >> 2) * 64; wn = (wid & 3) * 64; }
    else         { wm = (wid >> 1) * 32; wn = (wid & 1) * 64; }

    float acc[WI][8][4];
#pragma unroll
    for (int i = 0; i < WI; i++)
#pragma unroll
        for (int j = 0; j < 8; j++)
#pragma unroll
            for (int q = 0; q < 4; q++) acc[i][j][q] = 0.f;

    int nch = K >> 6;

    auto load_a = [&](int s, int c) {
        if (c >= nch) return;
        uint32_t stg = base + s * STGB;
        int k0 = c << 6;
#pragma unroll
        for (int it = 0; it < 4; it++) {
            int i = tid + it * 256;
            int row = i >> 3, cc = i & 7;
            uint32_t o = swz(row, cc);
            size_t gi = (size_t)(m0 + row) * K + k0 + cc * 8;
            cpa(stg + o, Ahi + gi);
            cpa(stg + OFF_ALO + o, Alo + gi);
        }
    };
    auto load_bh = [&](int s, int c) {
        if (c >= nch) return;
        uint32_t stg = base + s * STGB;
        int k0 = c << 6;
#pragma unroll
        for (int it = 0; it < NT / 32; it++) {
            int i = tid + it * 256;
            int row = i >> 3, cc = i & 7;
            size_t gi = (size_t)(n0 + row) * K + k0 + cc * 8;
            cpa(stg + OFF_BHI + swz(row, cc), Bhi + gi);
        }
    };
    auto load_bl = [&](int s, int c) {
        if (c >= nch) return;
        uint32_t stg = base + s * STGB;
        int k0 = c << 6;
#pragma unroll
        for (int it = 0; it < NT / 32; it++) {
            int i = tid + it * 256;
            int row = i >> 3, cc = i & 7;
            size_t gi = (size_t)(n0 + row) * K + k0 + cc * 8;
            cpa(stg + OFF_BHI + NT * 128 + swz(row, cc), Blo + gi);
        }
    };

    auto compute_ks = [&](int ks, uint32_t stg) {
        uint32_t ah[WI][4], al[WI][4];
        int ar = wm + (lane & 15);
        int ac = ks * 2 + (lane >> 4);
#pragma unroll
        for (int i = 0; i < WI; i++) {
            uint32_t adr = stg + swz(ar + i * 16, ac);
            ldsm4(ah[i], adr);
            ldsm4(al[i], adr + OFF_ALO);
        }
        int jj = (lane >> 4);
        int brr = wn + (lane & 7);
        int bcc = ks * 2 + ((lane >> 3) & 1);
#pragma unroll
        for (int j2 = 0; j2 < 4; j2++) {
            uint32_t bh[4], bl[4];
            uint32_t adr = stg + OFF_BHI + swz(brr + (j2 * 2 + jj) * 8, bcc);
            ldsm4(bh, adr);
            ldsm4(bl, adr + NT * 128);
            int ja = j2 * 2, jb = ja + 1;
#pragma unroll
            for (int i = 0; i < WI; i++) mma_bf16(acc[i][ja], ah[i], bh + 0);
#pragma unroll
            for (int i = 0; i < WI; i++) mma_bf16(acc[i][jb], ah[i], bh + 2);
#pragma unroll
            for (int i = 0; i < WI; i++) mma_bf16(acc[i][ja], ah[i], bl + 0);
#pragma unroll
            for (int i = 0; i < WI; i++) mma_bf16(acc[i][jb], ah[i], bl + 2);
#pragma unroll
            for (int i = 0; i < WI; i++) mma_bf16(acc[i][ja], al[i], bh + 0);
#pragma unroll
            for (int i = 0; i < WI; i++) mma_bf16(acc[i][jb], al[i], bh + 2);
        }
    };

    load_a(0, 0); load_bh(0, 0); load_bl(0, 0); cpa_commit();

    for (int c = 0; c < nch; c++) {
        int s = c & 1;
        uint32_t stg = base + s * STGB;
        cpa_wait<0>();
        __syncthreads();
        compute_ks(0, stg);
        load_a(s ^ 1, c + 1);
        load_bh(s ^ 1, c + 1);
        compute_ks(1, stg);
        load_bl(s ^ 1, c + 1);
        cpa_commit();
        compute_ks(2, stg);
        compute_ks(3, stg);
    }

    int rb = m0 + wm, cb = n0 + wn;
#pragma unroll
    for (int i = 0; i < WI; i++)
#pragma unroll
        for (int j = 0; j < 8; j++) {
            int r0 = rb + i * 16 + (lane >> 2);
            int c0 = cb + j * 8 + (lane & 3) * 2;
            float bx = bias[c0], by = bias[c0 + 1];
#pragma unroll
            for (int h = 0; h < 2; h++) {
                int row = r0 + h * 8;
                float v0 = acc[i][j][h * 2 + 0] + bx;
                float v1 = acc[i][j][h * 2 + 1] + by;
                if (MODE == 0) {
                    size_t o = (size_t)e * sCe + (size_t)row * ldc + c0;
                    v0 = gelu_fast(v0); v1 = gelu_fast(v1);
                    split2(v0, v1, (bf16*)out0 + o, (bf16*)out1 + o);
                } else if (MODE == 1) {
                    int t = g_inv[e * CAP + row];
                    if (t >= 0) {
                        float g = g_gate[t];
                        size_t o = (size_t)t * ldc + c0;
                        split2(v0 * g, v1 * g, (bf16*)out0 + o, (bf16*)out1 + o);
                    }
                } else {
                    size_t oo = (size_t)row * ldc + c0;
                    if (c0 < colmax)     ((float*)out0)[oo] = v0;
                    if (c0 + 1 < colmax) ((float*)out0)[oo + 1] = v1;
                }
            }
        }
}

// ---------------- launch ----------------
extern "C" void kernel_launch(void* const* d_in, const int* in_sizes, int n_in,
                              void* d_out, int out_size) {
    const float* x  = (const float*)d_in[0];
    const float* Wg = (const float*)d_in[1];
    const float* W1 = (const float*)d_in[2];
    const float* b1 = (const float*)d_in[3];
    const float* W2 = (const float*)d_in[4];
    const float* b2 = (const float*)d_in[5];
    const float* Wl = (const float*)d_in[6];
    const float* bl = (const float*)d_in[7];
    float* out = (float*)d_out;

    const int GEMM_SMEM4 = 2 * (32768 + 2 * 256 * 128) + 128;  // 196736
    const int GEMM_SMEM2 = 2 * (32768 + 2 * 128 * 128) + 128;  // 131200

    static int smem_set = 0;
    if (!smem_set) {
        cudaFuncSetAttribute((const void*)k_mgemm<0,4>, cudaFuncAttributeMaxDynamicSharedMemorySize, GEMM_SMEM4);
        cudaFuncSetAttribute((const void*)k_mgemm<1,4>, cudaFuncAttributeMaxDynamicSharedMemorySize, GEMM_SMEM4);
        cudaFuncSetAttribute((const void*)k_mgemm<2,2>, cudaFuncAttributeMaxDynamicSharedMemorySize, GEMM_SMEM2);
        smem_set = 1;
    }

    bf16 *w1h, *w1l, *w2h, *w2l, *wlh, *wll, *dh, *dl, *hh, *hl, *yh, *yl;
    cudaGetSymbolAddress((void**)&w1h, g_w1t_hi); cudaGetSymbolAddress((void**)&w1l, g_w1t_lo);
    cudaGetSymbolAddress((void**)&w2h, g_w2t_hi); cudaGetSymbolAddress((void**)&w2l, g_w2t_lo);
    cudaGetSymbolAddress((void**)&wlh, g_wlt_hi); cudaGetSymbolAddress((void**)&wll, g_wlt_lo);
    cudaGetSymbolAddress((void**)&dh, g_disp_hi); cudaGetSymbolAddress((void**)&dl, g_disp_lo);
    cudaGetSymbolAddress((void**)&hh, g_h_hi);    cudaGetSymbolAddress((void**)&hl, g_h_lo);
    cudaGetSymbolAddress((void**)&yh, g_y_hi);    cudaGetSymbolAddress((void**)&yl, g_y_lo);

    k_gate<<<NB_GATE, 256>>>(x, Wg);
    k_scan<<<E_NUM, 256>>>();
    k_big<<<BIG_TOT, 256>>>(x, W1, W2, Wl);

    // FFN1: [CAP,1024] x [4096,1024]^T -> h bf16 hi/lo (bias+gelu)
    k_mgemm<0,4><<<dim3(H_DIM/256, CAP/128, E_NUM), 256, GEMM_SMEM4>>>(
        dh, dl, (size_t)CAP*D_DIM, w1h, w1l, (size_t)H_DIM*D_DIM,
        b1, H_DIM, hh, hl, (size_t)CAP*H_DIM, D_DIM, H_DIM, H_DIM);
    // FFN2: [CAP,4096] x [1024,4096]^T -> y bf16 hi/lo at token rows (fused combine)
    k_mgemm<1,4><<<dim3(D_DIM/256, CAP/128, E_NUM), 256, GEMM_SMEM4>>>(
        hh, hl, (size_t)CAP*H_DIM, w2h, w2l, (size_t)D_DIM*H_DIM,
        b2, D_DIM, yh, yl, 0, H_DIM, D_DIM, D_DIM);

    // classifier (NT=128): [16384,1024] x [1024,1024]^T -> out [16384,1000]
    k_mgemm<2,2><<<dim3(1024/128, N_TOK/128, 1), 256, GEMM_SMEM2>>>(
        yh, yl, 0, wlh, wll, 0,
        bl, 0, out, nullptr, 0, D_DIM, NC_DIM, NC_DIM);

    k_loss<<<1, 32>>>(out, out_size);
}